// round 6
// baseline (speedup 1.0000x reference)
#include <cuda_runtime.h>
#include <cuda_bf16.h>
#include <math.h>
#include <stdint.h>

// ---------------- static scratch (no allocations allowed) ----------------
#define MAXN   50048            // padded
#define MAXE   800000

__device__ float g_x0[MAXN * 128];
__device__ float g_x1[MAXN * 128];
__device__ __nv_bfloat16 g_Ah[(size_t)MAXN * 768];   // agg hi split (bf16)
__device__ __nv_bfloat16 g_Al[(size_t)MAXN * 768];   // agg lo split
__device__ float g_t[MAXN * 8];          // [N,6] padded to 8
__device__ __nv_bfloat16 g_Bh[4][768 * 128];  // B split hi: [l][n*768+k]
__device__ __nv_bfloat16 g_Bl[4][768 * 128];  // B split lo
__device__ int   g_deg[MAXN];
__device__ int   g_off[MAXN + 1];
__device__ int   g_cur[MAXN];
__device__ int   g_src[MAXE];
__device__ int   g_dst[MAXE];

// ---------------- helpers ----------------
__device__ __forceinline__ uint32_t smem_u32(const void* p) {
    uint32_t a;
    asm("{ .reg .u64 t; cvta.to.shared.u64 t, %1; cvt.u32.u64 %0, t; }" : "=r"(a) : "l"(p));
    return a;
}
__device__ __forceinline__ void cpa16(uint32_t dst, const void* src) {
    asm volatile("cp.async.cg.shared.global [%0], [%1], 16;" :: "r"(dst), "l"(src));
}
#define CP_COMMIT() asm volatile("cp.async.commit_group;")
#define LDMX4(r, addr)                                                          \
    asm volatile("ldmatrix.sync.aligned.m8n8.x4.shared.b16 {%0,%1,%2,%3}, [%4];"\
        : "=r"((r)[0]), "=r"((r)[1]), "=r"((r)[2]), "=r"((r)[3]) : "r"(addr))
#define MMA_BF16(d, a, b0, b1)                                                  \
    asm volatile("mma.sync.aligned.m16n8k16.row.col.f32.bf16.bf16.f32 "         \
        "{%0,%1,%2,%3}, {%4,%5,%6,%7}, {%8,%9}, {%0,%1,%2,%3};"                 \
        : "+f"((d)[0]), "+f"((d)[1]), "+f"((d)[2]), "+f"((d)[3])                \
        : "r"((a)[0]), "r"((a)[1]), "r"((a)[2]), "r"((a)[3]), "r"(b0), "r"(b1))

__device__ __forceinline__ uint32_t pack_bf2(float x, float y) {
    __nv_bfloat16 hx = __float2bfloat16_rn(x), hy = __float2bfloat16_rn(y);
    return (uint32_t)__bfloat16_as_ushort(hx) | ((uint32_t)__bfloat16_as_ushort(hy) << 16);
}
__device__ __forceinline__ void split4(float4 v, uint2& hi, uint2& lo) {
    __nv_bfloat16 h0 = __float2bfloat16_rn(v.x), h1 = __float2bfloat16_rn(v.y);
    __nv_bfloat16 h2 = __float2bfloat16_rn(v.z), h3 = __float2bfloat16_rn(v.w);
    hi.x = (uint32_t)__bfloat16_as_ushort(h0) | ((uint32_t)__bfloat16_as_ushort(h1) << 16);
    hi.y = (uint32_t)__bfloat16_as_ushort(h2) | ((uint32_t)__bfloat16_as_ushort(h3) << 16);
    lo.x = pack_bf2(v.x - __bfloat162float(h0), v.y - __bfloat162float(h1));
    lo.y = pack_bf2(v.z - __bfloat162float(h2), v.w - __bfloat162float(h3));
}

// ---------------- CSR construction ----------------
__global__ void k_zero_deg(int n) {
    int i = blockIdx.x * blockDim.x + threadIdx.x;
    if (i < n) g_deg[i] = 0;
}
__global__ void k_hist(const int* __restrict__ ei, int e) {
    int i = blockIdx.x * blockDim.x + threadIdx.x;
    if (i < e) atomicAdd(&g_deg[ei[e + i]], 1);
}
__global__ void k_scan(int n) {
    __shared__ int sm[1024];
    __shared__ int base;
    if (threadIdx.x == 0) base = 0;
    __syncthreads();
    for (int start = 0; start < n; start += 1024) {
        int i = start + threadIdx.x;
        int v = (i < n) ? g_deg[i] : 0;
        sm[threadIdx.x] = v;
        __syncthreads();
        for (int ofs = 1; ofs < 1024; ofs <<= 1) {
            int t = 0;
            if ((int)threadIdx.x >= ofs) t = sm[threadIdx.x - ofs];
            __syncthreads();
            sm[threadIdx.x] += t;
            __syncthreads();
        }
        if (i < n) {
            int excl = base + sm[threadIdx.x] - v;
            g_off[i] = excl;
            g_cur[i] = excl;
        }
        int total = sm[1023];
        __syncthreads();
        if (threadIdx.x == 0) base += total;
        __syncthreads();
    }
    if (threadIdx.x == 0) g_off[n] = base;
}
__global__ void k_scatter(const int* __restrict__ ei, int e) {
    int i = blockIdx.x * blockDim.x + threadIdx.x;
    if (i < e) {
        int dst = ei[e + i];
        int p = atomicAdd(&g_cur[dst], 1);
        g_src[p] = ei[i];
        g_dst[p] = dst;
    }
}

// ---------------- per-layer weight split ----------------
__global__ void k_wsplit(int l, const float* __restrict__ Wg) {
    int idx = blockIdx.x * blockDim.x + threadIdx.x;
    if (idx >= 768 * 128) return;
    int n = idx / 768, k = idx - n * 768;
    int h = k >> 7, kk = k & 127;
    float v = Wg[h * 16384 + n * 128 + kk];
    __nv_bfloat16 hi = __float2bfloat16_rn(v);
    g_Bh[l][idx] = hi;
    g_Bl[l][idx] = __float2bfloat16_rn(v - __bfloat162float(hi));
}

// ---------------- input layer ----------------
__global__ void k_x0(const float* __restrict__ pos, const float* __restrict__ nrm,
                     const float* __restrict__ w1, const float* __restrict__ b1, int n) {
    int gid = blockIdx.x * blockDim.x + threadIdx.x;
    if (gid >= n * 128) return;
    int i = gid >> 7, d = gid & 127;
    const float* wr = w1 + d * 6;
    float a = b1[d];
    a = fmaf(pos[i * 3 + 0], wr[0], a);
    a = fmaf(pos[i * 3 + 1], wr[1], a);
    a = fmaf(pos[i * 3 + 2], wr[2], a);
    a = fmaf(nrm[i * 3 + 0], wr[3], a);
    a = fmaf(nrm[i * 3 + 1], wr[4], a);
    a = fmaf(nrm[i * 3 + 2], wr[5], a);
    g_x0[(size_t)i * 128 + d] = fmaxf(a, 0.f);
}

// ---------------- t = x @ u.T ----------------
__global__ void k_t(int sel, const float* __restrict__ u, int n) {
    int gw = (blockIdx.x * blockDim.x + threadIdx.x) >> 5;
    int lane = threadIdx.x & 31;
    if (gw >= n) return;
    const float* x = sel ? g_x1 : g_x0;
    float4 xv = *(const float4*)(x + (size_t)gw * 128 + lane * 4);
    float a0, a1, a2, a3, a4, a5;
    {
        float4 w;
        w = *(const float4*)(u + 0 * 128 + lane * 4); a0 = xv.x*w.x + xv.y*w.y + xv.z*w.z + xv.w*w.w;
        w = *(const float4*)(u + 1 * 128 + lane * 4); a1 = xv.x*w.x + xv.y*w.y + xv.z*w.z + xv.w*w.w;
        w = *(const float4*)(u + 2 * 128 + lane * 4); a2 = xv.x*w.x + xv.y*w.y + xv.z*w.z + xv.w*w.w;
        w = *(const float4*)(u + 3 * 128 + lane * 4); a3 = xv.x*w.x + xv.y*w.y + xv.z*w.z + xv.w*w.w;
        w = *(const float4*)(u + 4 * 128 + lane * 4); a4 = xv.x*w.x + xv.y*w.y + xv.z*w.z + xv.w*w.w;
        w = *(const float4*)(u + 5 * 128 + lane * 4); a5 = xv.x*w.x + xv.y*w.y + xv.z*w.z + xv.w*w.w;
    }
    #pragma unroll
    for (int o = 16; o; o >>= 1) {
        a0 += __shfl_xor_sync(0xffffffffu, a0, o);
        a1 += __shfl_xor_sync(0xffffffffu, a1, o);
        a2 += __shfl_xor_sync(0xffffffffu, a2, o);
        a3 += __shfl_xor_sync(0xffffffffu, a3, o);
        a4 += __shfl_xor_sync(0xffffffffu, a4, o);
        a5 += __shfl_xor_sync(0xffffffffu, a5, o);
    }
    if (lane == 0) {
        float* tp = g_t + (size_t)gw * 8;
        tp[0] = a0; tp[1] = a1; tp[2] = a2; tp[3] = a3; tp[4] = a4; tp[5] = a5;
        tp[6] = 0.f; tp[7] = 0.f;
    }
}

// ---------------- fused softmax + aggregation (warp per dst node) ----------------
// Per 4-edge group: lane (oct=lane/8, h=lane%8) computes exp for (edge oct, head h);
// octet butterfly -> denominator; one rcp per octet; shfl-broadcast q to all lanes;
// then each lane accumulates its 4 feature columns over the 4 edges.
#define AGG_FMA(q0, q1, q2, q3, q4, q5, xv)                                                      \
    do {                                                                                         \
        a0.x = fmaf(q0, xv.x, a0.x); a0.y = fmaf(q0, xv.y, a0.y);                                \
        a0.z = fmaf(q0, xv.z, a0.z); a0.w = fmaf(q0, xv.w, a0.w);                                \
        a1.x = fmaf(q1, xv.x, a1.x); a1.y = fmaf(q1, xv.y, a1.y);                                \
        a1.z = fmaf(q1, xv.z, a1.z); a1.w = fmaf(q1, xv.w, a1.w);                                \
        a2.x = fmaf(q2, xv.x, a2.x); a2.y = fmaf(q2, xv.y, a2.y);                                \
        a2.z = fmaf(q2, xv.z, a2.z); a2.w = fmaf(q2, xv.w, a2.w);                                \
        a3.x = fmaf(q3, xv.x, a3.x); a3.y = fmaf(q3, xv.y, a3.y);                                \
        a3.z = fmaf(q3, xv.z, a3.z); a3.w = fmaf(q3, xv.w, a3.w);                                \
        a4.x = fmaf(q4, xv.x, a4.x); a4.y = fmaf(q4, xv.y, a4.y);                                \
        a4.z = fmaf(q4, xv.z, a4.z); a4.w = fmaf(q4, xv.w, a4.w);                                \
        a5.x = fmaf(q5, xv.x, a5.x); a5.y = fmaf(q5, xv.y, a5.y);                                \
        a5.z = fmaf(q5, xv.z, a5.z); a5.w = fmaf(q5, xv.w, a5.w);                                \
    } while (0)

__global__ void k_agg(int sel, const float* __restrict__ cvec, int n) {
    int gw = (blockIdx.x * blockDim.x + threadIdx.x) >> 5;
    int lane = threadIdx.x & 31;
    if (gw >= n) return;
    const float* x = sel ? g_x1 : g_x0;
    int beg = g_off[gw], end = g_off[gw + 1];
    const int oct = lane >> 3, h8 = lane & 7;

    float tD = g_t[(size_t)gw * 8 + h8];
    float bb = ((h8 < 6) ? cvec[h8] : 0.f) - tD;
    float invdeg = 1.f / fmaxf((float)(end - beg), 1.f);

    float4 a0 = make_float4(0,0,0,0), a1 = a0, a2 = a0, a3 = a0, a4 = a0, a5 = a0;

    for (int ep = beg; ep < end; ep += 4) {
        int nE = min(4, end - ep);
        int eo = (oct < nE) ? oct : 0;
        int sIdx = g_src[ep + eo];
        float tv = g_t[(size_t)sIdx * 8 + h8];
        float e = (h8 < 6 && oct < nE) ? __expf(tv + bb) : 0.f;
        float S = e;
        S += __shfl_xor_sync(0xffffffffu, S, 1);
        S += __shfl_xor_sync(0xffffffffu, S, 2);
        S += __shfl_xor_sync(0xffffffffu, S, 4);
        float invv = 0.f;
        if (h8 == 0) invv = __fdividef(invdeg, S);   // one MUFU per octet
        invv = __shfl_sync(0xffffffffu, invv, oct * 8);
        float q = e * invv;

        #pragma unroll
        for (int j = 0; j < 4; j++) {
            if (j >= nE) break;   // uniform across warp
            int s  = __shfl_sync(0xffffffffu, sIdx, j * 8);
            float q0 = __shfl_sync(0xffffffffu, q, j * 8 + 0);
            float q1 = __shfl_sync(0xffffffffu, q, j * 8 + 1);
            float q2 = __shfl_sync(0xffffffffu, q, j * 8 + 2);
            float q3 = __shfl_sync(0xffffffffu, q, j * 8 + 3);
            float q4 = __shfl_sync(0xffffffffu, q, j * 8 + 4);
            float q5 = __shfl_sync(0xffffffffu, q, j * 8 + 5);
            float4 xv = *(const float4*)(x + (size_t)s * 128 + lane * 4);
            AGG_FMA(q0, q1, q2, q3, q4, q5, xv);
        }
    }
    size_t base = (size_t)gw * 768 + lane * 4;
    uint2 hi, lo;
    split4(a0, hi, lo); *(uint2*)(g_Ah + base + 0 * 128) = hi; *(uint2*)(g_Al + base + 0 * 128) = lo;
    split4(a1, hi, lo); *(uint2*)(g_Ah + base + 1 * 128) = hi; *(uint2*)(g_Al + base + 1 * 128) = lo;
    split4(a2, hi, lo); *(uint2*)(g_Ah + base + 2 * 128) = hi; *(uint2*)(g_Al + base + 2 * 128) = lo;
    split4(a3, hi, lo); *(uint2*)(g_Ah + base + 3 * 128) = hi; *(uint2*)(g_Al + base + 3 * 128) = lo;
    split4(a4, hi, lo); *(uint2*)(g_Ah + base + 4 * 128) = hi; *(uint2*)(g_Al + base + 4 * 128) = lo;
    split4(a5, hi, lo); *(uint2*)(g_Ah + base + 5 * 128) = hi; *(uint2*)(g_Al + base + 5 * 128) = lo;
}

// ---------------- GEMM: relu(A[N,768] @ B.T + bias), bf16 3-product split ----------------
// CTA 128(M) x 64(N) tile for wave balance (grid 782). BK=16, 48 chunks,
// 2-stage cp.async, ldmatrix fragments. smem rows 48B stride: conflict-free.
#define LDP 24

__global__ void __launch_bounds__(256, 2) k_gemm_mma(int l, const float* __restrict__ bias, int outsel) {
    __shared__ __nv_bfloat16 sA[2][2][128][LDP];
    __shared__ __nv_bfloat16 sB[2][2][64][LDP];

    const int tid = threadIdx.x;
    const int wid = tid >> 5, lane = tid & 31;
    const int warpM = wid & 3, warpN = wid >> 2;    // 4 x 2 -> warp tile 32x32
    const int g = lane >> 2, tig = lane & 3;
    const int blockRow = (blockIdx.x >> 1) * 128;
    const int blockCol = (blockIdx.x & 1) * 64;

    const int rowS = tid >> 1, halfS = tid & 1;
    const __nv_bfloat16* gBh = g_Bh[l] + (size_t)blockCol * 768;
    const __nv_bfloat16* gBl = g_Bl[l] + (size_t)blockCol * 768;

    float acc[2][4][4];
    #pragma unroll
    for (int mt = 0; mt < 2; mt++)
        #pragma unroll
        for (int nt = 0; nt < 4; nt++)
            #pragma unroll
            for (int j = 0; j < 4; j++) acc[mt][nt][j] = 0.f;

    const int lj = lane >> 3, lrr = lane & 7;
    const int lrow = (lj & 1) * 8 + lrr;
    const int lcol = (lj >> 1) * 8;

    auto stage_load = [&](int c, int st) {
        int k0 = c * 16;
        cpa16(smem_u32(&sA[st][0][rowS][halfS * 8]),
              g_Ah + (size_t)(blockRow + rowS) * 768 + k0 + halfS * 8);
        cpa16(smem_u32(&sA[st][1][rowS][halfS * 8]),
              g_Al + (size_t)(blockRow + rowS) * 768 + k0 + halfS * 8);
        if (tid < 128) {
            cpa16(smem_u32(&sB[st][0][rowS][halfS * 8]),
                  gBh + (size_t)rowS * 768 + k0 + halfS * 8);
            cpa16(smem_u32(&sB[st][1][rowS][halfS * 8]),
                  gBl + (size_t)rowS * 768 + k0 + halfS * 8);
        }
        CP_COMMIT();
    };

    stage_load(0, 0);

    for (int c = 0; c < 48; c++) {
        int st = c & 1;
        if (c < 47) {
            stage_load(c + 1, st ^ 1);
            asm volatile("cp.async.wait_group 1;");
        } else {
            asm volatile("cp.async.wait_group 0;");
        }
        __syncthreads();

        uint32_t aF[2][2][4];
        #pragma unroll
        for (int s = 0; s < 2; s++)
            #pragma unroll
            for (int mt = 0; mt < 2; mt++)
                LDMX4(aF[s][mt], smem_u32(&sA[st][s][warpM * 32 + mt * 16 + lrow][lcol]));
        #pragma unroll
        for (int ntp = 0; ntp < 2; ntp++) {
            uint32_t bh[4], bl[4];
            LDMX4(bh, smem_u32(&sB[st][0][warpN * 32 + ntp * 16 + lrow][lcol]));
            LDMX4(bl, smem_u32(&sB[st][1][warpN * 32 + ntp * 16 + lrow][lcol]));
            #pragma unroll
            for (int mt = 0; mt < 2; mt++) {
                float* dE = acc[mt][2 * ntp];
                float* dO = acc[mt][2 * ntp + 1];
                MMA_BF16(dE, aF[0][mt], bh[0], bh[2]);
                MMA_BF16(dE, aF[0][mt], bl[0], bl[2]);
                MMA_BF16(dE, aF[1][mt], bh[0], bh[2]);
                MMA_BF16(dO, aF[0][mt], bh[1], bh[3]);
                MMA_BF16(dO, aF[0][mt], bl[1], bl[3]);
                MMA_BF16(dO, aF[1][mt], bh[1], bh[3]);
            }
        }
        __syncthreads();
    }

    float* C = outsel ? g_x1 : g_x0;
    #pragma unroll
    for (int mt = 0; mt < 2; mt++) {
        int r0 = blockRow + warpM * 32 + mt * 16 + g;
        #pragma unroll
        for (int nt = 0; nt < 4; nt++) {
            int col = blockCol + warpN * 32 + nt * 8 + tig * 2;
            float b0 = bias[col], b1 = bias[col + 1];
            float2 v0, v1;
            v0.x = fmaxf(acc[mt][nt][0] + b0, 0.f);
            v0.y = fmaxf(acc[mt][nt][1] + b1, 0.f);
            v1.x = fmaxf(acc[mt][nt][2] + b0, 0.f);
            v1.y = fmaxf(acc[mt][nt][3] + b1, 0.f);
            *(float2*)&C[(size_t)r0 * 128 + col] = v0;
            *(float2*)&C[(size_t)(r0 + 8) * 128 + col] = v1;
        }
    }
}

// ---------------- output: out = x @ w2.T + b2 ----------------
__global__ void k_out(int sel, const float* __restrict__ w2, const float* __restrict__ b2,
                      float* __restrict__ out, int n) {
    int gw = (blockIdx.x * blockDim.x + threadIdx.x) >> 5;
    int lane = threadIdx.x & 31;
    if (gw >= n) return;
    const float* x = sel ? g_x1 : g_x0;
    float4 xv = *(const float4*)(x + (size_t)gw * 128 + lane * 4);
    float4 w;
    w = *(const float4*)(w2 + 0 * 128 + lane * 4);
    float a0 = xv.x * w.x + xv.y * w.y + xv.z * w.z + xv.w * w.w;
    w = *(const float4*)(w2 + 1 * 128 + lane * 4);
    float a1 = xv.x * w.x + xv.y * w.y + xv.z * w.z + xv.w * w.w;
    w = *(const float4*)(w2 + 2 * 128 + lane * 4);
    float a2 = xv.x * w.x + xv.y * w.y + xv.z * w.z + xv.w * w.w;
    #pragma unroll
    for (int o = 16; o; o >>= 1) {
        a0 += __shfl_xor_sync(0xffffffffu, a0, o);
        a1 += __shfl_xor_sync(0xffffffffu, a1, o);
        a2 += __shfl_xor_sync(0xffffffffu, a2, o);
    }
    if (lane == 0) {
        out[(size_t)gw * 3 + 0] = a0 + b2[0];
        out[(size_t)gw * 3 + 1] = a1 + b2[1];
        out[(size_t)gw * 3 + 2] = a2 + b2[2];
    }
}

// ---------------- launch ----------------
extern "C" void kernel_launch(void* const* d_in, const int* in_sizes, int n_in,
                              void* d_out, int out_size) {
    const float* pos = (const float*)d_in[0];
    const float* nrm = (const float*)d_in[1];
    const int*   ei  = (const int*)d_in[2];
    const float* w1  = (const float*)d_in[3];
    const float* b1  = (const float*)d_in[4];
    const float* w2  = (const float*)d_in[5];
    const float* b2  = (const float*)d_in[6];
    const float* Wg[4] = {(const float*)d_in[7],  (const float*)d_in[11],
                          (const float*)d_in[15], (const float*)d_in[19]};
    const float* u[4]  = {(const float*)d_in[8],  (const float*)d_in[12],
                          (const float*)d_in[16], (const float*)d_in[20]};
    const float* c[4]  = {(const float*)d_in[9],  (const float*)d_in[13],
                          (const float*)d_in[17], (const float*)d_in[21]};
    const float* bg[4] = {(const float*)d_in[10], (const float*)d_in[14],
                          (const float*)d_in[18], (const float*)d_in[22]};

    int n = in_sizes[0] / 3;   // 50000
    int e = in_sizes[2] / 2;   // 800000

    // CSR build
    k_zero_deg<<<(n + 255) / 256, 256>>>(n);
    k_hist<<<(e + 255) / 256, 256>>>(ei, e);
    k_scan<<<1, 1024>>>(n);
    k_scatter<<<(e + 255) / 256, 256>>>(ei, e);

    // per-layer weight hi/lo split
    for (int l = 0; l < 4; l++)
        k_wsplit<<<(768 * 128 + 255) / 256, 256>>>(l, Wg[l]);

    // input layer
    k_x0<<<(n * 128 + 255) / 256, 256>>>(pos, nrm, w1, b1, n);

    // 4 feast layers (ping-pong x between g_x0 / g_x1)
    int sel = 0;
    int warp_blocks = (n * 32 + 255) / 256;
    int gemm_blocks = ((n + 127) / 128) * 2;     // 782 (N split in two 64-col tiles)
    for (int l = 0; l < 4; l++) {
        k_t<<<warp_blocks, 256>>>(sel, u[l], n);
        k_agg<<<warp_blocks, 256>>>(sel, c[l], n);
        k_gemm_mma<<<gemm_blocks, 256>>>(l, bg[l], 1 - sel);
        sel = 1 - sel;
    }

    // output projection
    k_out<<<warp_blocks, 256>>>(sel, w2, b2, (float*)d_out, n);
}